// round 1
// baseline (speedup 1.0000x reference)
#include <cuda_runtime.h>

#define NCLASS 128

// Global scratch (no allocations allowed).
__device__ float        g_colsum[NCLASS];
__device__ unsigned int g_counts[NCLASS];
__device__ float        g_picked;

__global__ void zero_scratch_kernel() {
    int i = threadIdx.x;
    if (i < NCLASS) {
        g_colsum[i] = 0.0f;
        g_counts[i] = 0u;
    }
    if (i == 0) g_picked = 0.0f;
}

// One warp per row. Lane l owns columns [4l, 4l+3] via a single float4 load.
__global__ __launch_bounds__(256) void loss_main_kernel(
    const float* __restrict__ pred,
    const int*   __restrict__ tgt,
    int n)
{
    __shared__ float        s_colsum[NCLASS];
    __shared__ unsigned int s_counts[NCLASS];
    __shared__ float        s_picked;

    const int tid  = threadIdx.x;
    const int lane = tid & 31;
    const int wrp  = tid >> 5;

    if (tid < NCLASS) { s_colsum[tid] = 0.0f; s_counts[tid] = 0u; }
    if (tid == 0) s_picked = 0.0f;
    __syncthreads();

    const int gwarp  = blockIdx.x * (blockDim.x >> 5) + wrp;
    const int nwarps = gridDim.x * (blockDim.x >> 5);

    float a0 = 0.f, a1 = 0.f, a2 = 0.f, a3 = 0.f;
    float pick = 0.f;

    // Main loop, 4-row manual unroll for MLP.
    int r = gwarp;
    for (; r + 3 * nwarps < n; r += 4 * nwarps) {
        const int r0 = r, r1 = r + nwarps, r2 = r + 2 * nwarps, r3 = r + 3 * nwarps;
        const float4 v0 = *reinterpret_cast<const float4*>(pred + (size_t)r0 * NCLASS + lane * 4);
        const float4 v1 = *reinterpret_cast<const float4*>(pred + (size_t)r1 * NCLASS + lane * 4);
        const float4 v2 = *reinterpret_cast<const float4*>(pred + (size_t)r2 * NCLASS + lane * 4);
        const float4 v3 = *reinterpret_cast<const float4*>(pred + (size_t)r3 * NCLASS + lane * 4);
        const int t0 = tgt[r0], t1 = tgt[r1], t2 = tgt[r2], t3 = tgt[r3];

        a0 += __expf(v0.x); a1 += __expf(v0.y); a2 += __expf(v0.z); a3 += __expf(v0.w);
        a0 += __expf(v1.x); a1 += __expf(v1.y); a2 += __expf(v1.z); a3 += __expf(v1.w);
        a0 += __expf(v2.x); a1 += __expf(v2.y); a2 += __expf(v2.z); a3 += __expf(v2.w);
        a0 += __expf(v3.x); a1 += __expf(v3.y); a2 += __expf(v3.z); a3 += __expf(v3.w);

        if ((t0 >> 2) == lane) {
            int k = t0 & 3;
            pick += (k == 0) ? v0.x : (k == 1) ? v0.y : (k == 2) ? v0.z : v0.w;
        }
        if ((t1 >> 2) == lane) {
            int k = t1 & 3;
            pick += (k == 0) ? v1.x : (k == 1) ? v1.y : (k == 2) ? v1.z : v1.w;
        }
        if ((t2 >> 2) == lane) {
            int k = t2 & 3;
            pick += (k == 0) ? v2.x : (k == 1) ? v2.y : (k == 2) ? v2.z : v2.w;
        }
        if ((t3 >> 2) == lane) {
            int k = t3 & 3;
            pick += (k == 0) ? v3.x : (k == 1) ? v3.y : (k == 2) ? v3.z : v3.w;
        }
        if (lane == 0) {
            atomicAdd(&s_counts[t0], 1u);
            atomicAdd(&s_counts[t1], 1u);
            atomicAdd(&s_counts[t2], 1u);
            atomicAdd(&s_counts[t3], 1u);
        }
    }
    // Tail
    for (; r < n; r += nwarps) {
        const float4 v = *reinterpret_cast<const float4*>(pred + (size_t)r * NCLASS + lane * 4);
        const int t = tgt[r];
        a0 += __expf(v.x); a1 += __expf(v.y); a2 += __expf(v.z); a3 += __expf(v.w);
        if ((t >> 2) == lane) {
            int k = t & 3;
            pick += (k == 0) ? v.x : (k == 1) ? v.y : (k == 2) ? v.z : v.w;
        }
        if (lane == 0) atomicAdd(&s_counts[t], 1u);
    }

    // Warp-reduce picked sum.
    #pragma unroll
    for (int off = 16; off > 0; off >>= 1)
        pick += __shfl_xor_sync(0xFFFFFFFFu, pick, off);
    if (lane == 0) atomicAdd(&s_picked, pick);

    // Per-lane column partials -> shared (cross-warp combine via smem atomics).
    atomicAdd(&s_colsum[lane * 4 + 0], a0);
    atomicAdd(&s_colsum[lane * 4 + 1], a1);
    atomicAdd(&s_colsum[lane * 4 + 2], a2);
    atomicAdd(&s_colsum[lane * 4 + 3], a3);
    __syncthreads();

    // Flush block partials to global.
    if (tid < NCLASS) {
        atomicAdd(&g_colsum[tid], s_colsum[tid]);
        if (s_counts[tid]) atomicAdd(&g_counts[tid], s_counts[tid]);
    }
    if (tid == 0) atomicAdd(&g_picked, s_picked);
}

__global__ void finalize_kernel(float* __restrict__ out, int n) {
    __shared__ float s_part[4];
    const int tid  = threadIdx.x;   // 128 threads
    const int lane = tid & 31;
    const int wrp  = tid >> 5;

    float diff = fabsf((float)g_counts[tid] - g_colsum[tid]);
    #pragma unroll
    for (int off = 16; off > 0; off >>= 1)
        diff += __shfl_xor_sync(0xFFFFFFFFu, diff, off);
    if (lane == 0) s_part[wrp] = diff;
    __syncthreads();
    if (tid == 0) {
        float extra = (s_part[0] + s_part[1] + s_part[2] + s_part[3]) / (float)n;
        float nll   = -g_picked / (float)n;
        out[0] = nll + extra;
    }
}

extern "C" void kernel_launch(void* const* d_in, const int* in_sizes, int n_in,
                              void* d_out, int out_size) {
    const float* pred = (const float*)d_in[0];
    const int*   tgt  = (const int*)d_in[1];
    float*       out  = (float*)d_out;
    const int n = in_sizes[1];  // number of rows / targets

    zero_scratch_kernel<<<1, 256>>>();

    // 2048 blocks x 8 warps = 16384 warps -> 64 rows/warp at N=1M (no tail).
    loss_main_kernel<<<2048, 256>>>(pred, tgt, n);

    finalize_kernel<<<1, NCLASS>>>(out, n);
}

// round 2
// speedup vs baseline: 1.1209x; 1.1209x over previous
#include <cuda_runtime.h>

#define NCLASS 128
#define NBLK   608          // 152 SMs x 4 resident blocks -> single wave
#define NTHR   256
#define UNROLL 8

// Global scratch — zero-initialized at module load; finalize re-zeros after
// consuming so every graph replay starts from a clean state.
__device__ float        g_colsum[NCLASS];
__device__ unsigned int g_counts[NCLASS];
__device__ float        g_picked;

// One warp per row. Lane l owns columns [4l, 4l+3] via one float4 load.
// 8-row unroll => 8 LDG.128 in flight per thread.
__global__ __launch_bounds__(NTHR, 4) void loss_main_kernel(
    const float* __restrict__ pred,
    const int*   __restrict__ tgt,
    int n)
{
    __shared__ float        s_colsum[NCLASS];
    __shared__ unsigned int s_counts[NCLASS];
    __shared__ float        s_picked;

    const int tid  = threadIdx.x;
    const int lane = tid & 31;
    const int wrp  = tid >> 5;

    if (tid < NCLASS) { s_colsum[tid] = 0.0f; s_counts[tid] = 0u; }
    if (tid == 0) s_picked = 0.0f;
    __syncthreads();

    const int gwarp = blockIdx.x * (NTHR >> 5) + wrp;
    const int W     = NBLK * (NTHR >> 5);     // total warps (stride)

    float a0 = 0.f, a1 = 0.f, a2 = 0.f, a3 = 0.f;
    float pick = 0.f;

    int r = gwarp;
    for (; r + (UNROLL - 1) * W < n; r += UNROLL * W) {
        float4 v[UNROLL];
        int    t[UNROLL];
        #pragma unroll
        for (int j = 0; j < UNROLL; j++) {
            const int rj = r + j * W;
            v[j] = __ldcs(reinterpret_cast<const float4*>(
                       pred + (size_t)rj * NCLASS + lane * 4));
            t[j] = tgt[rj];
        }
        #pragma unroll
        for (int j = 0; j < UNROLL; j++) {
            a0 += __expf(v[j].x); a1 += __expf(v[j].y);
            a2 += __expf(v[j].z); a3 += __expf(v[j].w);
            if ((t[j] >> 2) == lane) {
                const int k = t[j] & 3;
                pick += (k == 0) ? v[j].x : (k == 1) ? v[j].y
                      : (k == 2) ? v[j].z : v[j].w;
            }
            if (lane == j) atomicAdd(&s_counts[t[j]], 1u);  // lane j handles row j
        }
    }
    // Tail
    for (; r < n; r += W) {
        const float4 v = __ldcs(reinterpret_cast<const float4*>(
                             pred + (size_t)r * NCLASS + lane * 4));
        const int t = tgt[r];
        a0 += __expf(v.x); a1 += __expf(v.y); a2 += __expf(v.z); a3 += __expf(v.w);
        if ((t >> 2) == lane) {
            const int k = t & 3;
            pick += (k == 0) ? v.x : (k == 1) ? v.y : (k == 2) ? v.z : v.w;
        }
        if (lane == 0) atomicAdd(&s_counts[t], 1u);
    }

    // Warp-reduce picked sum.
    #pragma unroll
    for (int off = 16; off > 0; off >>= 1)
        pick += __shfl_xor_sync(0xFFFFFFFFu, pick, off);
    if (lane == 0) atomicAdd(&s_picked, pick);

    // Per-lane column partials -> shared (cross-warp combine).
    atomicAdd(&s_colsum[lane * 4 + 0], a0);
    atomicAdd(&s_colsum[lane * 4 + 1], a1);
    atomicAdd(&s_colsum[lane * 4 + 2], a2);
    atomicAdd(&s_colsum[lane * 4 + 3], a3);
    __syncthreads();

    // Flush block partials to global.
    if (tid < NCLASS) {
        atomicAdd(&g_colsum[tid], s_colsum[tid]);
        if (s_counts[tid]) atomicAdd(&g_counts[tid], s_counts[tid]);
    }
    if (tid == 0) atomicAdd(&g_picked, s_picked);
}

__global__ void finalize_kernel(float* __restrict__ out, int n) {
    __shared__ float s_part[4];
    const int tid  = threadIdx.x;   // 128 threads
    const int lane = tid & 31;
    const int wrp  = tid >> 5;

    float diff = fabsf((float)g_counts[tid] - g_colsum[tid]);
    const float picked = g_picked;

    // Re-zero scratch for the next graph replay (after reads above).
    g_colsum[tid] = 0.0f;
    g_counts[tid] = 0u;
    if (tid == 0) g_picked = 0.0f;

    #pragma unroll
    for (int off = 16; off > 0; off >>= 1)
        diff += __shfl_xor_sync(0xFFFFFFFFu, diff, off);
    if (lane == 0) s_part[wrp] = diff;
    __syncthreads();
    if (tid == 0) {
        const float extra = (s_part[0] + s_part[1] + s_part[2] + s_part[3]) / (float)n;
        out[0] = -picked / (float)n + extra;
    }
}

extern "C" void kernel_launch(void* const* d_in, const int* in_sizes, int n_in,
                              void* d_out, int out_size) {
    const float* pred = (const float*)d_in[0];
    const int*   tgt  = (const int*)d_in[1];
    float*       out  = (float*)d_out;
    const int n = in_sizes[1];  // number of rows / targets

    loss_main_kernel<<<NBLK, NTHR>>>(pred, tgt, n);
    finalize_kernel<<<1, NCLASS>>>(out, n);
}

// round 3
// speedup vs baseline: 1.1247x; 1.0033x over previous
#include <cuda_runtime.h>

#define NCLASS 128
#define NBLK   608          // 152 SMs x 4 resident blocks -> single wave
#define NTHR   256
#define UNROLL 8

// Global scratch — zero-initialized at module load; finalize re-zeros after
// consuming so every graph replay starts from a clean state.
__device__ float        g_colsum[NCLASS];
__device__ unsigned int g_counts[NCLASS];
__device__ float        g_picked;

// One warp per row. Lane l owns columns [4l, 4l+3] via one float4 load.
// 8-row unroll => 8 LDG.128 in flight per thread.
__global__ __launch_bounds__(NTHR, 4) void loss_main_kernel(
    const float* __restrict__ pred,
    const int*   __restrict__ tgt,
    int n)
{
    __shared__ float        s_colsum[NCLASS];
    __shared__ unsigned int s_counts[NCLASS];
    __shared__ float        s_picked;

    const int tid  = threadIdx.x;
    const int lane = tid & 31;
    const int wrp  = tid >> 5;

    if (tid < NCLASS) { s_colsum[tid] = 0.0f; s_counts[tid] = 0u; }
    if (tid == 0) s_picked = 0.0f;
    __syncthreads();

    const int gwarp = blockIdx.x * (NTHR >> 5) + wrp;
    const int W     = NBLK * (NTHR >> 5);     // total warps (stride)

    float a0 = 0.f, a1 = 0.f, a2 = 0.f, a3 = 0.f;
    float pick = 0.f;

    int r = gwarp;
    for (; r + (UNROLL - 1) * W < n; r += UNROLL * W) {
        float4 v[UNROLL];
        int    t[UNROLL];
        #pragma unroll
        for (int j = 0; j < UNROLL; j++) {
            const int rj = r + j * W;
            v[j] = __ldcs(reinterpret_cast<const float4*>(
                       pred + (size_t)rj * NCLASS + lane * 4));
            t[j] = tgt[rj];
        }
        #pragma unroll
        for (int j = 0; j < UNROLL; j++) {
            a0 += __expf(v[j].x); a1 += __expf(v[j].y);
            a2 += __expf(v[j].z); a3 += __expf(v[j].w);
            if ((t[j] >> 2) == lane) {
                const int k = t[j] & 3;
                pick += (k == 0) ? v[j].x : (k == 1) ? v[j].y
                      : (k == 2) ? v[j].z : v[j].w;
            }
            if (lane == j) atomicAdd(&s_counts[t[j]], 1u);  // lane j handles row j
        }
    }
    // Tail
    for (; r < n; r += W) {
        const float4 v = __ldcs(reinterpret_cast<const float4*>(
                             pred + (size_t)r * NCLASS + lane * 4));
        const int t = tgt[r];
        a0 += __expf(v.x); a1 += __expf(v.y); a2 += __expf(v.z); a3 += __expf(v.w);
        if ((t >> 2) == lane) {
            const int k = t & 3;
            pick += (k == 0) ? v.x : (k == 1) ? v.y : (k == 2) ? v.z : v.w;
        }
        if (lane == 0) atomicAdd(&s_counts[t], 1u);
    }

    // Warp-reduce picked sum.
    #pragma unroll
    for (int off = 16; off > 0; off >>= 1)
        pick += __shfl_xor_sync(0xFFFFFFFFu, pick, off);
    if (lane == 0) atomicAdd(&s_picked, pick);

    // Per-lane column partials -> shared (cross-warp combine).
    atomicAdd(&s_colsum[lane * 4 + 0], a0);
    atomicAdd(&s_colsum[lane * 4 + 1], a1);
    atomicAdd(&s_colsum[lane * 4 + 2], a2);
    atomicAdd(&s_colsum[lane * 4 + 3], a3);
    __syncthreads();

    // Flush block partials to global.
    if (tid < NCLASS) {
        atomicAdd(&g_colsum[tid], s_colsum[tid]);
        if (s_counts[tid]) atomicAdd(&g_counts[tid], s_counts[tid]);
    }
    if (tid == 0) atomicAdd(&g_picked, s_picked);
}

__global__ void finalize_kernel(float* __restrict__ out, int n) {
    __shared__ float s_part[4];
    const int tid  = threadIdx.x;   // 128 threads
    const int lane = tid & 31;
    const int wrp  = tid >> 5;

    float diff = fabsf((float)g_counts[tid] - g_colsum[tid]);
    const float picked = g_picked;

    // Re-zero scratch for the next graph replay (after reads above).
    g_colsum[tid] = 0.0f;
    g_counts[tid] = 0u;
    if (tid == 0) g_picked = 0.0f;

    #pragma unroll
    for (int off = 16; off > 0; off >>= 1)
        diff += __shfl_xor_sync(0xFFFFFFFFu, diff, off);
    if (lane == 0) s_part[wrp] = diff;
    __syncthreads();
    if (tid == 0) {
        const float extra = (s_part[0] + s_part[1] + s_part[2] + s_part[3]) / (float)n;
        out[0] = -picked / (float)n + extra;
    }
}

extern "C" void kernel_launch(void* const* d_in, const int* in_sizes, int n_in,
                              void* d_out, int out_size) {
    const float* pred = (const float*)d_in[0];
    const int*   tgt  = (const int*)d_in[1];
    float*       out  = (float*)d_out;
    const int n = in_sizes[1];  // number of rows / targets

    loss_main_kernel<<<NBLK, NTHR>>>(pred, tgt, n);
    finalize_kernel<<<1, NCLASS>>>(out, n);
}